// round 1
// baseline (speedup 1.0000x reference)
#include <cuda_runtime.h>
#include <cstdint>

#define EPSBN 1e-3f

// Intermediate y = relu(bn1(conv(x))) : (64, 512, 128) fp32 = 16.8 MB (fits L2)
__device__ float g_y[64 * 512 * 128];

// Packed f32x2 FMA: d.lo += a.lo*b.lo ; d.hi += a.hi*b.hi   (2x fp32 throughput)
__device__ __forceinline__ void ffma2(unsigned long long& d, unsigned long long a,
                                      unsigned long long b) {
    asm("fma.rn.f32x2 %0, %1, %2, %0;" : "+l"(d) : "l"(a), "l"(b));
}
__device__ __forceinline__ unsigned long long dup2(float v) {
    unsigned long long r;
    asm("mov.b64 %0, {%1, %1};" : "=l"(r) : "f"(v));
    return r;
}
__device__ __forceinline__ float lo32(unsigned long long v) {
    return __uint_as_float((unsigned)(v & 0xffffffffu));
}
__device__ __forceinline__ float hi32(unsigned long long v) {
    return __uint_as_float((unsigned)(v >> 32));
}

// ============================================================================
// Stage 1: Conv1D(K=7, SAME) + BN1 + ReLU  -> g_y
// GEMM view: per (batch b, l-tile of 64): C[64 l, 128 f] = A[64, 448] * W[448, 128]
// A[m, k*64+c] = x[b, l0+m+k-3, c]   (zero padded)
// Block: 128 threads, micro-tile 8(l) x 8(f) per thread, f32x2-paired along f.
// ============================================================================
__global__ __launch_bounds__(128) void conv_bn_kernel(
    const float* __restrict__ x, const float* __restrict__ w,
    const float* __restrict__ cbias,
    const float* __restrict__ g1, const float* __restrict__ b1,
    const float* __restrict__ m1, const float* __restrict__ v1) {
    const int b = blockIdx.y;
    const int l0 = blockIdx.x * 64;

    __shared__ float xd[70 * 128];  // x slice, each value duplicated (dup-pairs)
    __shared__ float ws[16 * 128];  // weight K-chunk

    const int tid = threadIdx.x;
    const int tx = tid & 15;  // f-group: f = tx*8 .. tx*8+7
    const int ty = tid >> 4;  // l-group: m = ty*8 .. ty*8+7

    // Load x[b, l0-3 .. l0+66, 0:64] duplicated into smem
    const float* xb = x + (size_t)b * 512 * 64;
    for (int idx = tid; idx < 70 * 64; idx += 128) {
        const int i = idx >> 6, c = idx & 63;
        const int row = l0 - 3 + i;
        const float v = (row >= 0 && row < 512) ? xb[row * 64 + c] : 0.0f;
        *(unsigned long long*)&xd[i * 128 + 2 * c] = dup2(v);
    }

    unsigned long long acc[8][4];
#pragma unroll
    for (int i = 0; i < 8; i++)
#pragma unroll
        for (int p = 0; p < 4; p++) acc[i][p] = 0ull;

    for (int kc = 0; kc < 448; kc += 16) {
        // load weight chunk ws[16][128] (w is row-major [448][128])
#pragma unroll
        for (int q = 0; q < 4; q++) {
            const int e = q * 512 + tid * 4;
            *(float4*)&ws[e] = *(const float4*)&w[(kc + (e >> 7)) * 128 + (e & 127)];
        }
        __syncthreads();
#pragma unroll
        for (int kk = 0; kk < 16; kk++) {
            const int j = kc + kk;
            const int k = j >> 6, c = j & 63;
            const ulonglong2* wrow = (const ulonglong2*)&ws[kk * 128 + tx * 8];
            const ulonglong2 w01 = wrow[0];
            const ulonglong2 w23 = wrow[1];
#pragma unroll
            for (int i = 0; i < 8; i++) {
                const unsigned long long av =
                    *(const unsigned long long*)&xd[(ty * 8 + i + k) * 128 + 2 * c];
                ffma2(acc[i][0], av, w01.x);
                ffma2(acc[i][1], av, w01.y);
                ffma2(acc[i][2], av, w23.x);
                ffma2(acc[i][3], av, w23.y);
            }
        }
        __syncthreads();
    }

    // Epilogue: bias + BN1 + ReLU, write to g_y
#pragma unroll
    for (int p = 0; p < 4; p++) {
        const int f0 = tx * 8 + 2 * p;
        const float s0 = g1[f0] * rsqrtf(v1[f0] + EPSBN);
        const float s1 = g1[f0 + 1] * rsqrtf(v1[f0 + 1] + EPSBN);
        const float sh0 = (cbias[f0] - m1[f0]) * s0 + b1[f0];
        const float sh1 = (cbias[f0 + 1] - m1[f0 + 1]) * s1 + b1[f0 + 1];
#pragma unroll
        for (int i = 0; i < 8; i++) {
            const int l = l0 + ty * 8 + i;
            float* yp = &g_y[(size_t)b * 65536 + l * 128 + f0];
            yp[0] = fmaxf(fmaf(lo32(acc[i][p]), s0, sh0), 0.0f);
            yp[1] = fmaxf(fmaf(hi32(acc[i][p]), s1, sh1), 0.0f);
        }
    }
}

// ============================================================================
// Stage 2: LocallyConnected1D(K=7, VALID) + BN2 + ReLU
// Per output position l (506 blocks): C[64 b, 128 f] = P[64, 896] * Wl[896, 128]
// P row b = g_y[b, l:l+7, :]  -> contiguous 896 floats at g_y + b*65536 + l*128
// Wl = local_w + l*896*128 (row-major [896][128])
// ============================================================================
__global__ __launch_bounds__(128) void local_bn_kernel(
    const float* __restrict__ lw, const float* __restrict__ lb,
    const float* __restrict__ g2, const float* __restrict__ b2,
    const float* __restrict__ m2, const float* __restrict__ v2,
    float* __restrict__ out) {
    const int l = blockIdx.x;

    __shared__ float ws[16 * 128];  // weight K-chunk
    __shared__ float pd[16 * 128];  // patch K-chunk, duplicated pairs: pd[kk][2b..2b+1]

    const int tid = threadIdx.x;
    const int tx = tid & 15;  // f-group
    const int ty = tid >> 4;  // batch-group: m = ty*8 .. ty*8+7

    const float* Wb = lw + (size_t)l * 896 * 128;
    const int pb = tid >> 1, ph = tid & 1;
    const float* Prow = g_y + (size_t)pb * 65536 + l * 128 + ph * 8;

    unsigned long long acc[8][4];
#pragma unroll
    for (int i = 0; i < 8; i++)
#pragma unroll
        for (int p = 0; p < 4; p++) acc[i][p] = 0ull;

    for (int kc = 0; kc < 896; kc += 16) {
        // weight chunk
#pragma unroll
        for (int q = 0; q < 4; q++) {
            const int e = q * 512 + tid * 4;
            *(float4*)&ws[e] = *(const float4*)&Wb[(kc + (e >> 7)) * 128 + (e & 127)];
        }
        // patch chunk (duplicated): thread covers batch pb, kk rows ph*8 .. ph*8+7
        {
            const float4 p0 = *(const float4*)&Prow[kc];
            const float4 p1 = *(const float4*)&Prow[kc + 4];
            const int col = 2 * pb;
            const int r0 = ph * 8;
            *(unsigned long long*)&pd[(r0 + 0) * 128 + col] = dup2(p0.x);
            *(unsigned long long*)&pd[(r0 + 1) * 128 + col] = dup2(p0.y);
            *(unsigned long long*)&pd[(r0 + 2) * 128 + col] = dup2(p0.z);
            *(unsigned long long*)&pd[(r0 + 3) * 128 + col] = dup2(p0.w);
            *(unsigned long long*)&pd[(r0 + 4) * 128 + col] = dup2(p1.x);
            *(unsigned long long*)&pd[(r0 + 5) * 128 + col] = dup2(p1.y);
            *(unsigned long long*)&pd[(r0 + 6) * 128 + col] = dup2(p1.z);
            *(unsigned long long*)&pd[(r0 + 7) * 128 + col] = dup2(p1.w);
        }
        __syncthreads();
#pragma unroll
        for (int kk = 0; kk < 16; kk++) {
            const ulonglong2* wrow = (const ulonglong2*)&ws[kk * 128 + tx * 8];
            const ulonglong2 w01 = wrow[0];
            const ulonglong2 w23 = wrow[1];
#pragma unroll
            for (int i = 0; i < 8; i++) {
                const unsigned long long av =
                    *(const unsigned long long*)&pd[kk * 128 + 2 * (ty * 8 + i)];
                ffma2(acc[i][0], av, w01.x);
                ffma2(acc[i][1], av, w01.y);
                ffma2(acc[i][2], av, w23.x);
                ffma2(acc[i][3], av, w23.y);
            }
        }
        __syncthreads();
    }

    // Epilogue: local bias + BN2 + ReLU
#pragma unroll
    for (int p = 0; p < 4; p++) {
        const int f0 = tx * 8 + 2 * p;
        const float s0 = g2[f0] * rsqrtf(v2[f0] + EPSBN);
        const float s1 = g2[f0 + 1] * rsqrtf(v2[f0 + 1] + EPSBN);
        const float sh0 = (lb[l * 128 + f0] - m2[f0]) * s0 + b2[f0];
        const float sh1 = (lb[l * 128 + f0 + 1] - m2[f0 + 1]) * s1 + b2[f0 + 1];
#pragma unroll
        for (int i = 0; i < 8; i++) {
            const int bat = ty * 8 + i;
            float* op = &out[(size_t)bat * 506 * 128 + l * 128 + f0];
            op[0] = fmaxf(fmaf(lo32(acc[i][p]), s0, sh0), 0.0f);
            op[1] = fmaxf(fmaf(hi32(acc[i][p]), s1, sh1), 0.0f);
        }
    }
}

extern "C" void kernel_launch(void* const* d_in, const int* in_sizes, int n_in,
                              void* d_out, int out_size) {
    const float* x      = (const float*)d_in[0];
    const float* conv_w = (const float*)d_in[1];
    const float* conv_b = (const float*)d_in[2];
    const float* g1     = (const float*)d_in[3];
    const float* b1     = (const float*)d_in[4];
    const float* m1     = (const float*)d_in[5];
    const float* v1     = (const float*)d_in[6];
    const float* lw     = (const float*)d_in[7];
    const float* lb     = (const float*)d_in[8];
    const float* g2     = (const float*)d_in[9];
    const float* b2     = (const float*)d_in[10];
    const float* m2     = (const float*)d_in[11];
    const float* v2     = (const float*)d_in[12];
    float* out = (float*)d_out;

    conv_bn_kernel<<<dim3(8, 64), 128>>>(x, conv_w, conv_b, g1, b1, m1, v1);
    local_bn_kernel<<<506, 128>>>(lw, lb, g2, b2, m2, v2, out);
}

// round 2
// speedup vs baseline: 1.2086x; 1.2086x over previous
#include <cuda_runtime.h>
#include <cstdint>

#define EPSBN 1e-3f

// Intermediate y = relu(bn1(conv(x))) : (64, 512, 128) fp32 = 16.8 MB (fits L2)
__device__ float g_y[64 * 512 * 128];

// Packed f32x2 FMA: d.lo += a.lo*b.lo ; d.hi += a.hi*b.hi  (2x fp32 throughput)
__device__ __forceinline__ void ffma2(unsigned long long& d, unsigned long long a,
                                      unsigned long long b) {
    asm("fma.rn.f32x2 %0, %1, %2, %0;" : "+l"(d) : "l"(a), "l"(b));
}
__device__ __forceinline__ unsigned long long dup2(float v) {
    unsigned long long r;
    asm("mov.b64 %0, {%1, %1};" : "=l"(r) : "f"(v));
    return r;
}
__device__ __forceinline__ float lo32(unsigned long long v) {
    return __uint_as_float((unsigned)(v & 0xffffffffu));
}
__device__ __forceinline__ float hi32(unsigned long long v) {
    return __uint_as_float((unsigned)(v >> 32));
}

// ============================================================================
// Stage 1: Conv1D(K=7, SAME) + BN1 + ReLU  -> g_y
// Per (batch b, l-tile 64): C[64 l, 128 f] = A[64, 448] * W[448, 128]
// A[m, k*64+c] = x[b, l0+m+k-3, c]. A stored UN-duplicated; dup in registers.
// 128 thr, 8(l) x 8(f) per thread, f32x2-paired along f. 4 blocks/SM.
// ============================================================================
__global__ __launch_bounds__(128, 4) void conv_bn_kernel(
    const float* __restrict__ x, const float* __restrict__ w,
    const float* __restrict__ cbias,
    const float* __restrict__ g1, const float* __restrict__ b1,
    const float* __restrict__ m1, const float* __restrict__ v1) {
    const int b = blockIdx.y;
    const int l0 = blockIdx.x * 64;

    __shared__ float xs[70 * 64];   // x slice (un-duplicated)
    __shared__ float ws[16 * 128];  // weight K-chunk

    const int tid = threadIdx.x;
    const int tx = tid & 15;  // f-group: f = tx*8 .. tx*8+7
    const int ty = tid >> 4;  // l-group: m = ty*8 .. ty*8+7

    // Load x[b, l0-3 .. l0+66, 0:64]
    const float* xb = x + (size_t)b * 512 * 64;
    for (int idx = tid; idx < 70 * 64; idx += 128) {
        const int i = idx >> 6, c = idx & 63;
        const int row = l0 - 3 + i;
        xs[idx] = (row >= 0 && row < 512) ? xb[row * 64 + c] : 0.0f;
    }

    unsigned long long acc[8][4];
#pragma unroll
    for (int i = 0; i < 8; i++)
#pragma unroll
        for (int p = 0; p < 4; p++) acc[i][p] = 0ull;

    // prefetch W chunk 0 into registers
    float4 wreg[4];
#pragma unroll
    for (int q = 0; q < 4; q++) {
        const int e = q * 512 + tid * 4;
        wreg[q] = *(const float4*)&w[(e >> 7) * 128 + (e & 127)];
    }

    for (int kc = 0; kc < 448; kc += 16) {
        // commit prefetched W chunk to smem
#pragma unroll
        for (int q = 0; q < 4; q++) {
            const int e = q * 512 + tid * 4;
            *(float4*)&ws[e] = wreg[q];
        }
        __syncthreads();
        // prefetch next chunk (overlaps with compute below)
        if (kc + 16 < 448) {
#pragma unroll
            for (int q = 0; q < 4; q++) {
                const int e = q * 512 + tid * 4;
                wreg[q] = *(const float4*)&w[(kc + 16 + (e >> 7)) * 128 + (e & 127)];
            }
        }
        const int k = kc >> 6;       // conv tap (fixed for whole chunk)
        const int cb = kc & 63;      // channel base
        const int abase = (ty * 8 + k) * 64 + cb;
#pragma unroll 4
        for (int kk = 0; kk < 16; kk++) {
            const ulonglong2 w01 = *(const ulonglong2*)&ws[kk * 128 + tx * 8];
            const ulonglong2 w23 = *(const ulonglong2*)&ws[kk * 128 + tx * 8 + 4];
#pragma unroll
            for (int i = 0; i < 8; i++) {
                const unsigned long long da = dup2(xs[abase + i * 64 + kk]);
                ffma2(acc[i][0], da, w01.x);
                ffma2(acc[i][1], da, w01.y);
                ffma2(acc[i][2], da, w23.x);
                ffma2(acc[i][3], da, w23.y);
            }
        }
        __syncthreads();
    }

    // Epilogue: bias + BN1 + ReLU
#pragma unroll
    for (int p = 0; p < 4; p++) {
        const int f0 = tx * 8 + 2 * p;
        const float s0 = g1[f0] * rsqrtf(v1[f0] + EPSBN);
        const float s1 = g1[f0 + 1] * rsqrtf(v1[f0 + 1] + EPSBN);
        const float sh0 = (cbias[f0] - m1[f0]) * s0 + b1[f0];
        const float sh1 = (cbias[f0 + 1] - m1[f0 + 1]) * s1 + b1[f0 + 1];
#pragma unroll
        for (int i = 0; i < 8; i++) {
            const int l = l0 + ty * 8 + i;
            float2 r;
            r.x = fmaxf(fmaf(lo32(acc[i][p]), s0, sh0), 0.0f);
            r.y = fmaxf(fmaf(hi32(acc[i][p]), s1, sh1), 0.0f);
            *(float2*)&g_y[(size_t)b * 65536 + l * 128 + f0] = r;
        }
    }
}

// ============================================================================
// Stage 2: LocallyConnected1D(K=7, VALID) + BN2 + ReLU
// Per l (506 blocks): C[64 b, 128 f] = P[64, 896] * Wl[896, 128]
// P row b contiguous at g_y + b*65536 + l*128. pd stored UN-duplicated,
// padded to 68/row for conflict-free vec reads; dup in registers.
// ============================================================================
__global__ __launch_bounds__(128, 4) void local_bn_kernel(
    const float* __restrict__ lw, const float* __restrict__ lb,
    const float* __restrict__ g2, const float* __restrict__ b2,
    const float* __restrict__ m2, const float* __restrict__ v2,
    float* __restrict__ out) {
    const int l = blockIdx.x;

    __shared__ float ws[16 * 128];  // weight K-chunk
    __shared__ float pd[16 * 68];   // patch K-chunk: pd[kk][batch], pad 68

    const int tid = threadIdx.x;
    const int tx = tid & 15;  // f-group
    const int ty = tid >> 4;  // batch-group: m = ty*8 .. ty*8+7

    const float* Wb = lw + (size_t)l * 896 * 128;
    const int pb = tid >> 1, ph = tid & 1;  // this thread loads batch pb, k-rows ph*8..+7
    const float* Prow = g_y + (size_t)pb * 65536 + l * 128 + ph * 8;

    unsigned long long acc[8][4];
#pragma unroll
    for (int i = 0; i < 8; i++)
#pragma unroll
        for (int p = 0; p < 4; p++) acc[i][p] = 0ull;

    // prefetch chunk 0
    float4 wreg[4], areg0, areg1;
#pragma unroll
    for (int q = 0; q < 4; q++) {
        const int e = q * 512 + tid * 4;
        wreg[q] = *(const float4*)&Wb[(e >> 7) * 128 + (e & 127)];
    }
    areg0 = *(const float4*)&Prow[0];
    areg1 = *(const float4*)&Prow[4];

    for (int kc = 0; kc < 896; kc += 16) {
        // commit prefetched chunk to smem
#pragma unroll
        for (int q = 0; q < 4; q++) {
            const int e = q * 512 + tid * 4;
            *(float4*)&ws[e] = wreg[q];
        }
        {
            const int r0 = ph * 8;
            pd[(r0 + 0) * 68 + pb] = areg0.x;
            pd[(r0 + 1) * 68 + pb] = areg0.y;
            pd[(r0 + 2) * 68 + pb] = areg0.z;
            pd[(r0 + 3) * 68 + pb] = areg0.w;
            pd[(r0 + 4) * 68 + pb] = areg1.x;
            pd[(r0 + 5) * 68 + pb] = areg1.y;
            pd[(r0 + 6) * 68 + pb] = areg1.z;
            pd[(r0 + 7) * 68 + pb] = areg1.w;
        }
        __syncthreads();
        // prefetch next chunk (overlaps compute)
        if (kc + 16 < 896) {
#pragma unroll
            for (int q = 0; q < 4; q++) {
                const int e = q * 512 + tid * 4;
                wreg[q] = *(const float4*)&Wb[(kc + 16 + (e >> 7)) * 128 + (e & 127)];
            }
            areg0 = *(const float4*)&Prow[kc + 16];
            areg1 = *(const float4*)&Prow[kc + 20];
        }
#pragma unroll 4
        for (int kk = 0; kk < 16; kk++) {
            const ulonglong2 w01 = *(const ulonglong2*)&ws[kk * 128 + tx * 8];
            const ulonglong2 w23 = *(const ulonglong2*)&ws[kk * 128 + tx * 8 + 4];
            const float4 a0 = *(const float4*)&pd[kk * 68 + ty * 8];
            const float4 a1 = *(const float4*)&pd[kk * 68 + ty * 8 + 4];
            const float av[8] = {a0.x, a0.y, a0.z, a0.w, a1.x, a1.y, a1.z, a1.w};
#pragma unroll
            for (int i = 0; i < 8; i++) {
                const unsigned long long da = dup2(av[i]);
                ffma2(acc[i][0], da, w01.x);
                ffma2(acc[i][1], da, w01.y);
                ffma2(acc[i][2], da, w23.x);
                ffma2(acc[i][3], da, w23.y);
            }
        }
        __syncthreads();
    }

    // Epilogue: local bias + BN2 + ReLU
#pragma unroll
    for (int p = 0; p < 4; p++) {
        const int f0 = tx * 8 + 2 * p;
        const float s0 = g2[f0] * rsqrtf(v2[f0] + EPSBN);
        const float s1 = g2[f0 + 1] * rsqrtf(v2[f0 + 1] + EPSBN);
        const float sh0 = (lb[l * 128 + f0] - m2[f0]) * s0 + b2[f0];
        const float sh1 = (lb[l * 128 + f0 + 1] - m2[f0 + 1]) * s1 + b2[f0 + 1];
#pragma unroll
        for (int i = 0; i < 8; i++) {
            const int bat = ty * 8 + i;
            float2 r;
            r.x = fmaxf(fmaf(lo32(acc[i][p]), s0, sh0), 0.0f);
            r.y = fmaxf(fmaf(hi32(acc[i][p]), s1, sh1), 0.0f);
            *(float2*)&out[(size_t)bat * 506 * 128 + l * 128 + f0] = r;
        }
    }
}

extern "C" void kernel_launch(void* const* d_in, const int* in_sizes, int n_in,
                              void* d_out, int out_size) {
    const float* x      = (const float*)d_in[0];
    const float* conv_w = (const float*)d_in[1];
    const float* conv_b = (const float*)d_in[2];
    const float* g1     = (const float*)d_in[3];
    const float* b1     = (const float*)d_in[4];
    const float* m1     = (const float*)d_in[5];
    const float* v1     = (const float*)d_in[6];
    const float* lw     = (const float*)d_in[7];
    const float* lb     = (const float*)d_in[8];
    const float* g2     = (const float*)d_in[9];
    const float* b2     = (const float*)d_in[10];
    const float* m2     = (const float*)d_in[11];
    const float* v2     = (const float*)d_in[12];
    float* out = (float*)d_out;

    conv_bn_kernel<<<dim3(8, 64), 128>>>(x, conv_w, conv_b, g1, b1, m1, v1);
    local_bn_kernel<<<506, 128>>>(lw, lb, g2, b2, m2, v2, out);
}